// round 15
// baseline (speedup 1.0000x reference)
#include <cuda_runtime.h>
#include <cuda_fp16.h>
#include <math.h>
#include <stdint.h>

#define N_NODES 50000
#define N_EDGES 1600000
#define E_TOT   (N_EDGES + N_NODES)
#define IN_DIM  256
#define HID     128
#define HEADS   4
#define OUT_DIM 2
#define NEG_SLOPE 0.2f
#define NB_SCAN ((N_NODES + 255) / 256)   // 196 (must be <= 256)

#define SA 264                        // smem row stride in halves (528B)
#define GEMM_SMEM (2 * 128 * SA * 2)  // A + B tiles = 135168 B

// ---------------- device scratch ---------------------------------------------
__device__ __half  g_xp1h[N_NODES * HID];
__device__ float4  g_as1[N_NODES];
__device__ float4  g_ad1[N_NODES];
__device__ float4  g_n2[N_NODES];
__device__ __half  g_wth[128 * SA];
__device__ float   g_sigf[IN_DIM];
__device__ int     g_cnt[N_NODES];
__device__ int     g_excl[N_NODES];
__device__ int     g_bsum[NB_SCAN];
__device__ int     g_rowstart[N_NODES + 1];
__device__ int     g_rankv[N_EDGES];
__device__ int     g_srcs[E_TOT];
__device__ int     g_is64;

__device__ __forceinline__ float leaky(float e) { return e > 0.f ? e : NEG_SLOPE * e; }

__device__ __forceinline__ int block_scan_incl_256(int v, int* smem8) {
    int lane = threadIdx.x & 31, wid = threadIdx.x >> 5;
    int x = v;
    #pragma unroll
    for (int o = 1; o < 32; o <<= 1) {
        int y = __shfl_up_sync(0xffffffffu, x, o);
        if (lane >= o) x += y;
    }
    if (lane == 31) smem8[wid] = x;
    __syncthreads();
    if (wid == 0 && lane < 8) {
        int w = smem8[lane];
        #pragma unroll
        for (int o = 1; o < 8; o <<= 1) {
            int y = __shfl_up_sync(0xffu, w, o);
            if (lane >= o) w += y;
        }
        smem8[lane] = w;
    }
    __syncthreads();
    if (wid > 0) x += smem8[wid - 1];
    return x;
}

// ---------------- prep: W1^T -> fp16, sigmoid(fi), zero cnt, dtype probe ------
__global__ void prep_k(const float* __restrict__ W1, const float* __restrict__ fi,
                       const int* __restrict__ ei32) {
    int i = blockIdx.x * 256 + threadIdx.x;
    if (i < IN_DIM * HID) {
        int k = i >> 7, n = i & 127;
        g_wth[n * SA + k] = __float2half_rn(W1[i]);
    }
    if (i < IN_DIM) g_sigf[i] = 1.0f / (1.0f + __expf(-fi[i]));
    if (i < N_NODES) g_cnt[i] = 0;
    if (i == 0) {
        int all0 = 1;
        for (int k = 0; k < 64; k++)
            if (ei32[2 * k + 1] != 0) all0 = 0;
        g_is64 = all0;   // int64 node ids < 50000 -> odd words all zero
    }
}

// ---------------- layer-1 GEMM: warp-level mma.sync ----------------------------
__global__ __launch_bounds__(256, 1) void gemm_mma_k(
    const float* __restrict__ x,
    const float* __restrict__ attS, const float* __restrict__ attD)
{
    extern __shared__ __half sm[];
    __half* As = sm;                 // [128][SA]
    __half* Bs = sm + 128 * SA;      // [128][SA]
    __shared__ float sigf[IN_DIM];
    __shared__ float ssa[HID], ssd[HID];

    int tid = threadIdx.x;
    sigf[tid] = g_sigf[tid];
    if (tid < HID) { ssa[tid] = attS[tid]; ssd[tid] = attD[tid]; }

    {
        const uint4* wsrc = (const uint4*)g_wth;
        uint4* bd = (uint4*)Bs;
        #pragma unroll 4
        for (int i = tid; i < 128 * SA / 8; i += 256) bd[i] = wsrc[i];
    }
    __syncthreads();

    int row0 = blockIdx.x * 128;
    for (int f4 = tid; f4 < 8192; f4 += 256) {
        int r = f4 >> 6, c4 = (f4 & 63) * 4;
        int gr = row0 + r;
        float4 v = make_float4(0.f, 0.f, 0.f, 0.f);
        if (gr < N_NODES) v = *(const float4*)&x[(size_t)gr * IN_DIM + c4];
        float4 s = *(float4*)&sigf[c4];
        __half2 h0 = __floats2half2_rn(v.x * s.x, v.y * s.y);
        __half2 h1 = __floats2half2_rn(v.z * s.z, v.w * s.w);
        uint2 u;
        u.x = *(unsigned*)&h0;
        u.y = *(unsigned*)&h1;
        *(uint2*)&As[r * SA + c4] = u;
    }
    __syncthreads();

    int lane = tid & 31, wid = tid >> 5;
    int wm = wid >> 2, wn = wid & 3;
    int r4 = lane >> 2, q = lane & 3;
    int m_base = wm * 64;
    int n_base = wn * 32;

    float c[4][4][4];
    #pragma unroll
    for (int i = 0; i < 4; i++)
        #pragma unroll
        for (int j = 0; j < 4; j++)
            #pragma unroll
            for (int e = 0; e < 4; e++) c[i][j][e] = 0.f;

    const __half* a_base = As + (m_base + r4) * SA + 2 * q;
    const __half* b_base = Bs + (n_base + r4) * SA + 2 * q;

    #pragma unroll 1
    for (int ks = 0; ks < 16; ks++) {
        int k0 = ks * 16;
        unsigned bf[4][2];
        #pragma unroll
        for (int j = 0; j < 4; j++) {
            bf[j][0] = *(const unsigned*)&b_base[j * 8 * SA + k0];
            bf[j][1] = *(const unsigned*)&b_base[j * 8 * SA + k0 + 8];
        }
        #pragma unroll
        for (int i = 0; i < 4; i++) {
            const __half* ap = a_base + i * 16 * SA + k0;
            unsigned a0 = *(const unsigned*)ap;
            unsigned a1 = *(const unsigned*)(ap + 8 * SA);
            unsigned a2 = *(const unsigned*)(ap + 8);
            unsigned a3 = *(const unsigned*)(ap + 8 * SA + 8);
            #pragma unroll
            for (int j = 0; j < 4; j++) {
                asm volatile(
                    "mma.sync.aligned.m16n8k16.row.col.f32.f16.f16.f32 "
                    "{%0,%1,%2,%3}, {%4,%5,%6,%7}, {%8,%9}, {%0,%1,%2,%3};"
                    : "+f"(c[i][j][0]), "+f"(c[i][j][1]),
                      "+f"(c[i][j][2]), "+f"(c[i][j][3])
                    : "r"(a0), "r"(a1), "r"(a2), "r"(a3),
                      "r"(bf[j][0]), "r"(bf[j][1]));
            }
        }
    }
    __syncthreads();

    unsigned* stage = (unsigned*)sm;
    const int SST = 68;

    #pragma unroll
    for (int i = 0; i < 4; i++) {
        int mr = m_base + i * 16 + r4;
        float psl = 0.f, pdl = 0.f, psh = 0.f, pdh = 0.f;
        #pragma unroll
        for (int j = 0; j < 4; j++) {
            int col = n_base + j * 8 + 2 * q;
            float sa0 = ssa[col], sa1 = ssa[col + 1];
            float sd0 = ssd[col], sd1 = ssd[col + 1];
            psl += c[i][j][0] * sa0 + c[i][j][1] * sa1;
            pdl += c[i][j][0] * sd0 + c[i][j][1] * sd1;
            psh += c[i][j][2] * sa0 + c[i][j][3] * sa1;
            pdh += c[i][j][2] * sd0 + c[i][j][3] * sd1;
            __half2 lo = __floats2half2_rn(c[i][j][0], c[i][j][1]);
            __half2 hi = __floats2half2_rn(c[i][j][2], c[i][j][3]);
            stage[mr * SST + ((n_base + j * 8) >> 1) + q]       = *(unsigned*)&lo;
            stage[(mr + 8) * SST + ((n_base + j * 8) >> 1) + q] = *(unsigned*)&hi;
        }
        #pragma unroll
        for (int o = 1; o < 4; o <<= 1) {
            psl += __shfl_xor_sync(0xffffffffu, psl, o);
            pdl += __shfl_xor_sync(0xffffffffu, pdl, o);
            psh += __shfl_xor_sync(0xffffffffu, psh, o);
            pdh += __shfl_xor_sync(0xffffffffu, pdh, o);
        }
        if (q == 0) {
            int gl = row0 + mr, gh = gl + 8;
            if (gl < N_NODES) {
                ((float*)&g_as1[gl])[wn] = psl;
                ((float*)&g_ad1[gl])[wn] = pdl;
            }
            if (gh < N_NODES) {
                ((float*)&g_as1[gh])[wn] = psh;
                ((float*)&g_ad1[gh])[wn] = pdh;
            }
        }
    }
    __syncthreads();

    unsigned* gx = (unsigned*)g_xp1h;
    for (int idx = tid; idx < 128 * 64; idx += 256) {
        int r = idx >> 6, cc = idx & 63;
        int gr = row0 + r;
        if (gr < N_NODES) gx[gr * 64 + cc] = stage[r * SST + cc];
    }
}

// ---------------- CSR build: rank pass + 2-phase scan + placement --------------
__global__ void rank_k(const void* __restrict__ eiv) {
    int i4 = (blockIdx.x * blockDim.x + threadIdx.x) * 4;
    if (i4 >= N_EDGES) return;
    int d0, d1, d2, d3;
    if (g_is64) {
        const longlong2* p = (const longlong2*)eiv + (N_EDGES + i4) / 2;
        longlong2 q0 = p[0], q1 = p[1];
        d0 = (int)q0.x; d1 = (int)q0.y; d2 = (int)q1.x; d3 = (int)q1.y;
    } else {
        int4 v = *((const int4*)((const int*)eiv + N_EDGES + i4));
        d0 = v.x; d1 = v.y; d2 = v.z; d3 = v.w;
    }
    int4 r;
    r.x = atomicAdd(&g_cnt[d0], 1);
    r.y = atomicAdd(&g_cnt[d1], 1);
    r.z = atomicAdd(&g_cnt[d2], 1);
    r.w = atomicAdd(&g_cnt[d3], 1);
    *(int4*)&g_rankv[i4] = r;
}

__global__ __launch_bounds__(256) void scanA_k() {
    __shared__ int smem8[8];
    int i = blockIdx.x * 256 + threadIdx.x;
    int v = (i < N_NODES) ? g_cnt[i] + 1 : 0;   // +1 self-loop at row end
    int incl = block_scan_incl_256(v, smem8);
    if (i < N_NODES) g_excl[i] = incl - v;
    if (threadIdx.x == 255) g_bsum[blockIdx.x] = incl;
}

// scanC: each block derives its own offset by reducing g_bsum[0..bid) in-block
__global__ __launch_bounds__(256) void scanC_k() {
    __shared__ int red[256];
    int bid = blockIdx.x, t = threadIdx.x;
    red[t] = (t < bid) ? g_bsum[t] : 0;
    __syncthreads();
    #pragma unroll
    for (int s = 128; s > 0; s >>= 1) {
        if (t < s) red[t] += red[t + s];
        __syncthreads();
    }
    int prefix = red[0];
    int i = bid * 256 + t;
    if (i < N_NODES) {
        int r = g_excl[i] + prefix;
        g_rowstart[i] = r;
        g_srcs[r + g_cnt[i]] = i;     // self-loop slot (last in row)
    }
    if (bid == NB_SCAN - 1 && t == 0)
        g_rowstart[N_NODES] = prefix + g_bsum[bid];   // == E_TOT
}

// placement: no atomics, position = rowstart[dst] + rank
__global__ void place_k(const void* __restrict__ eiv) {
    int i4 = (blockIdx.x * blockDim.x + threadIdx.x) * 4;
    if (i4 >= N_EDGES) return;
    int s0, s1, s2, s3, d0, d1, d2, d3;
    if (g_is64) {
        const longlong2* ps = (const longlong2*)eiv + i4 / 2;
        const longlong2* pd = (const longlong2*)eiv + (N_EDGES + i4) / 2;
        longlong2 a0 = ps[0], a1 = ps[1], b0 = pd[0], b1 = pd[1];
        s0 = (int)a0.x; s1 = (int)a0.y; s2 = (int)a1.x; s3 = (int)a1.y;
        d0 = (int)b0.x; d1 = (int)b0.y; d2 = (int)b1.x; d3 = (int)b1.y;
    } else {
        int4 sv = *((const int4*)((const int*)eiv + i4));
        int4 dv = *((const int4*)((const int*)eiv + N_EDGES + i4));
        s0 = sv.x; s1 = sv.y; s2 = sv.z; s3 = sv.w;
        d0 = dv.x; d1 = dv.y; d2 = dv.z; d3 = dv.w;
    }
    int4 r = *(const int4*)&g_rankv[i4];
    g_srcs[g_rowstart[d0] + r.x] = s0;
    g_srcs[g_rowstart[d1] + r.y] = s1;
    g_srcs[g_rowstart[d2] + r.z] = s2;
    g_srcs[g_rowstart[d3] + r.w] = s3;
}

// ---------------- layer-1 gather: 2 warps per node (halved edge depth) ---------
// Warp pair (2k, 2k+1) owns node k; each warp processes a contiguous half of the
// node's edge range (R13-style chunks inside), then the pair combines via smem.
// Grid is exact (100000 warps = 12500 blocks), so no early returns.
__global__ __launch_bounds__(256) void gather1_k(
    const float* __restrict__ b1, const float* __restrict__ W2,
    const float* __restrict__ aS2, const float* __restrict__ aD2)
{
    __shared__ float4 sw[8][32];
    __shared__ int    ssrc[8][32];
    __shared__ float  comb[4][32][9];   // [node-in-block][lane][z, c0..c7]

    int wslot = threadIdx.x >> 5;
    int gwarp = blockIdx.x * 8 + wslot;
    int node = gwarp >> 1;
    int half = gwarp & 1;
    int nib  = wslot >> 1;
    int l = threadIdx.x & 31;

    int rs = g_rowstart[node], re = g_rowstart[node + 1];
    int len = re - rs;
    int mid = rs + ((len + 1) >> 1);
    int mrs = half ? mid : rs;
    int mre = half ? re  : mid;
    float4 ad = g_ad1[node];

    int h  = l >> 4;
    int hl = l & 15;
    int head = hl >> 2;

    float z = 0.f;
    float c[8];
    #pragma unroll
    for (int i = 0; i < 8; i++) c[i] = 0.f;

    for (int jc = mrs; jc < mre; jc += 32) {
        int idx = jc + l;
        if (idx < mre) {
            int s = g_srcs[idx];
            float4 a = g_as1[s];
            sw[wslot][l] = make_float4(__expf(leaky(a.x + ad.x)),
                                       __expf(leaky(a.y + ad.y)),
                                       __expf(leaky(a.z + ad.z)),
                                       __expf(leaky(a.w + ad.w)));
            ssrc[wslot][l] = s;
        }
        __syncwarp();
        int cnt = mre - jc; if (cnt > 32) cnt = 32;
        #pragma unroll 4
        for (int e = h; e < cnt; e += 2) {
            int s = ssrc[wslot][e];
            float4 w4 = sw[wslot][e];
            float wv = (head == 0) ? w4.x : (head == 1) ? w4.y
                     : (head == 2) ? w4.z : w4.w;
            uint4 pk = *(const uint4*)&g_xp1h[s * HID + 8 * hl];
            float2 f0 = __half22float2(*(__half2*)&pk.x);
            float2 f1 = __half22float2(*(__half2*)&pk.y);
            float2 f2 = __half22float2(*(__half2*)&pk.z);
            float2 f3 = __half22float2(*(__half2*)&pk.w);
            z += wv;
            c[0] += wv * f0.x; c[1] += wv * f0.y;
            c[2] += wv * f1.x; c[3] += wv * f1.y;
            c[4] += wv * f2.x; c[5] += wv * f2.y;
            c[6] += wv * f3.x; c[7] += wv * f3.y;
        }
        __syncwarp();
    }

    // combine the two half-warps of this warp
    z += __shfl_xor_sync(0xffffffffu, z, 16);
    #pragma unroll
    for (int i = 0; i < 8; i++) c[i] += __shfl_xor_sync(0xffffffffu, c[i], 16);

    // cross-warp combine: odd warp publishes, even warp accumulates + epilogue
    if (half) {
        comb[nib][l][0] = z;
        #pragma unroll
        for (int i = 0; i < 8; i++) comb[nib][l][1 + i] = c[i];
    }
    __syncthreads();
    if (half) return;

    z += comb[nib][l][0];
    #pragma unroll
    for (int i = 0; i < 8; i++) c[i] += comb[nib][l][1 + i];

    float inv = 1.0f / (z + 1e-16f);
    float4 bA = *(const float4*)&b1[8 * hl];
    float4 bB = *(const float4*)&b1[8 * hl + 4];
    float hh[8];
    hh[0] = c[0] * inv + bA.x; hh[1] = c[1] * inv + bA.y;
    hh[2] = c[2] * inv + bA.z; hh[3] = c[3] * inv + bA.w;
    hh[4] = c[4] * inv + bB.x; hh[5] = c[5] * inv + bB.y;
    hh[6] = c[6] * inv + bB.z; hh[7] = c[7] * inv + bB.w;
    #pragma unroll
    for (int i = 0; i < 8; i++) hh[i] = hh[i] > 0.f ? hh[i] : expm1f(hh[i]);

    float p0 = 0.f, p1 = 0.f;
    #pragma unroll
    for (int i = 0; i < 8; i += 2) {
        float4 w = *(const float4*)&W2[(8 * hl + i) * 2];
        p0 += hh[i] * w.x + hh[i + 1] * w.z;
        p1 += hh[i] * w.y + hh[i + 1] * w.w;
    }
    #pragma unroll
    for (int o = 8; o > 0; o >>= 1) {
        p0 += __shfl_xor_sync(0xffffffffu, p0, o);
        p1 += __shfl_xor_sync(0xffffffffu, p1, o);
    }
    if (l == 0) {
        float as2 = p0 * aS2[0] + p1 * aS2[1];
        float ad2 = p0 * aD2[0] + p1 * aD2[1];
        g_n2[node] = make_float4(p0, p1, as2, ad2);
    }
}

// ---------------- layer-2 gather + output -------------------------------------
__global__ __launch_bounds__(256) void gather2_k(
    const float* __restrict__ b2, float* __restrict__ out)
{
    int gw = (blockIdx.x * blockDim.x + threadIdx.x) >> 5;
    int l = threadIdx.x & 31;
    if (gw >= N_NODES) return;
    int rs = g_rowstart[gw], re = g_rowstart[gw + 1];
    float ad = g_n2[gw].w;

    float z = 0.f, a0 = 0.f, a1 = 0.f;
    for (int j = rs + l; j < re; j += 32) {
        int s = __ldg(&g_srcs[j]);
        float4 n = __ldg(&g_n2[s]);
        float w = __expf(leaky(n.z + ad));
        z += w; a0 += w * n.x; a1 += w * n.y;
    }
    #pragma unroll
    for (int o = 16; o > 0; o >>= 1) {
        z  += __shfl_xor_sync(0xffffffffu, z, o);
        a0 += __shfl_xor_sync(0xffffffffu, a0, o);
        a1 += __shfl_xor_sync(0xffffffffu, a1, o);
    }
    if (l == 0) {
        float inv = 1.0f / (z + 1e-16f);
        out[gw * 2]     = a0 * inv + b2[0];
        out[gw * 2 + 1] = a1 * inv + b2[1];
    }
}

// ---------------- launch: R13 structure, split gather1 -------------------------
extern "C" void kernel_launch(void* const* d_in, const int* in_sizes, int n_in,
                              void* d_out, int out_size) {
    const float* x     = (const float*)d_in[0];
    const float* fi    = (const float*)d_in[1];
    const float* W1    = (const float*)d_in[2];
    const float* attS1 = (const float*)d_in[3];
    const float* attD1 = (const float*)d_in[4];
    const float* b1    = (const float*)d_in[5];
    const float* W2    = (const float*)d_in[6];
    const float* attS2 = (const float*)d_in[7];
    const float* attD2 = (const float*)d_in[8];
    const float* b2    = (const float*)d_in[9];
    const void*  ei    = (const void*)d_in[10];
    float* out = (float*)d_out;

    static cudaStream_t s2 = nullptr;
    static cudaEvent_t evFork = nullptr, evJoin = nullptr;
    if (s2 == nullptr) {
        cudaStreamCreateWithFlags(&s2, cudaStreamNonBlocking);
        cudaEventCreateWithFlags(&evFork, cudaEventDisableTiming);
        cudaEventCreateWithFlags(&evJoin, cudaEventDisableTiming);
        cudaFuncSetAttribute(gemm_mma_k, cudaFuncAttributeMaxDynamicSharedMemorySize, GEMM_SMEM);
    }

    int prep_threads = (N_NODES > IN_DIM * HID) ? N_NODES : IN_DIM * HID;
    prep_k<<<(prep_threads + 255) / 256, 256>>>(W1, fi, (const int*)ei);

    // fork after prep: chain B (CSR build) on s2, concurrent with the GEMM
    cudaEventRecord(evFork, 0);
    cudaStreamWaitEvent(s2, evFork, 0);
    rank_k<<<(N_EDGES / 4 + 255) / 256, 256, 0, s2>>>(ei);
    scanA_k<<<NB_SCAN, 256, 0, s2>>>();
    scanC_k<<<NB_SCAN, 256, 0, s2>>>();
    place_k<<<(N_EDGES / 4 + 255) / 256, 256, 0, s2>>>(ei);
    cudaEventRecord(evJoin, s2);

    // chain A on capture stream
    gemm_mma_k<<<(N_NODES + 127) / 128, 256, GEMM_SMEM>>>(x, attS1, attD1);

    // join: gathers need both chains
    cudaStreamWaitEvent(0, evJoin, 0);
    gather1_k<<<(N_NODES * 2 * 32) / 256, 256>>>(b1, W2, attS2, attD2);  // 12500 blocks exact
    gather2_k<<<(N_NODES * 32 + 255) / 256, 256>>>(b2, out);
}

// round 16
// speedup vs baseline: 1.0769x; 1.0769x over previous
#include <cuda_runtime.h>
#include <cuda_fp16.h>
#include <math.h>
#include <stdint.h>

#define N_NODES 50000
#define N_EDGES 1600000
#define E_TOT   (N_EDGES + N_NODES)
#define IN_DIM  256
#define HID     128
#define HEADS   4
#define OUT_DIM 2
#define NEG_SLOPE 0.2f
#define NB_SCAN ((N_NODES + 255) / 256)   // 196 (must be <= 256)

#define SA 264                        // smem row stride in halves (528B)
#define GEMM_SMEM (2 * 128 * SA * 2)  // A + B tiles = 135168 B

// ---------------- device scratch ---------------------------------------------
__device__ __half  g_xp1h[N_NODES * HID];
__device__ float4  g_as1[N_NODES];
__device__ float4  g_ad1[N_NODES];
__device__ float4  g_n2[N_NODES];
__device__ __half  g_wth[128 * SA];
__device__ float   g_sigf[IN_DIM];
__device__ int     g_cnt[N_NODES];
__device__ int     g_excl[N_NODES];
__device__ int     g_bsum[NB_SCAN];
__device__ int     g_rowstart[N_NODES + 1];
__device__ int     g_rankv[N_EDGES];
__device__ int     g_srcs[E_TOT];
__device__ int     g_is64;

__device__ __forceinline__ float leaky(float e) { return e > 0.f ? e : NEG_SLOPE * e; }

__device__ __forceinline__ int block_scan_incl_256(int v, int* smem8) {
    int lane = threadIdx.x & 31, wid = threadIdx.x >> 5;
    int x = v;
    #pragma unroll
    for (int o = 1; o < 32; o <<= 1) {
        int y = __shfl_up_sync(0xffffffffu, x, o);
        if (lane >= o) x += y;
    }
    if (lane == 31) smem8[wid] = x;
    __syncthreads();
    if (wid == 0 && lane < 8) {
        int w = smem8[lane];
        #pragma unroll
        for (int o = 1; o < 8; o <<= 1) {
            int y = __shfl_up_sync(0xffu, w, o);
            if (lane >= o) w += y;
        }
        smem8[lane] = w;
    }
    __syncthreads();
    if (wid > 0) x += smem8[wid - 1];
    return x;
}

// ---------------- prep: W1^T -> fp16, sigmoid(fi), zero cnt, dtype probe ------
__global__ void prep_k(const float* __restrict__ W1, const float* __restrict__ fi,
                       const int* __restrict__ ei32) {
    int i = blockIdx.x * 256 + threadIdx.x;
    if (i < IN_DIM * HID) {
        int k = i >> 7, n = i & 127;
        g_wth[n * SA + k] = __float2half_rn(W1[i]);
    }
    if (i < IN_DIM) g_sigf[i] = 1.0f / (1.0f + __expf(-fi[i]));
    if (i < N_NODES) g_cnt[i] = 0;
    if (i == 0) {
        int all0 = 1;
        for (int k = 0; k < 64; k++)
            if (ei32[2 * k + 1] != 0) all0 = 0;
        g_is64 = all0;   // int64 node ids < 50000 -> odd words all zero
    }
}

// ---------------- layer-1 GEMM: warp-level mma.sync ----------------------------
__global__ __launch_bounds__(256, 1) void gemm_mma_k(
    const float* __restrict__ x,
    const float* __restrict__ attS, const float* __restrict__ attD)
{
    extern __shared__ __half sm[];
    __half* As = sm;                 // [128][SA]
    __half* Bs = sm + 128 * SA;      // [128][SA]
    __shared__ float sigf[IN_DIM];
    __shared__ float ssa[HID], ssd[HID];

    int tid = threadIdx.x;
    sigf[tid] = g_sigf[tid];
    if (tid < HID) { ssa[tid] = attS[tid]; ssd[tid] = attD[tid]; }

    {
        const uint4* wsrc = (const uint4*)g_wth;
        uint4* bd = (uint4*)Bs;
        #pragma unroll 4
        for (int i = tid; i < 128 * SA / 8; i += 256) bd[i] = wsrc[i];
    }
    __syncthreads();

    int row0 = blockIdx.x * 128;
    for (int f4 = tid; f4 < 8192; f4 += 256) {
        int r = f4 >> 6, c4 = (f4 & 63) * 4;
        int gr = row0 + r;
        float4 v = make_float4(0.f, 0.f, 0.f, 0.f);
        if (gr < N_NODES) v = *(const float4*)&x[(size_t)gr * IN_DIM + c4];
        float4 s = *(float4*)&sigf[c4];
        __half2 h0 = __floats2half2_rn(v.x * s.x, v.y * s.y);
        __half2 h1 = __floats2half2_rn(v.z * s.z, v.w * s.w);
        uint2 u;
        u.x = *(unsigned*)&h0;
        u.y = *(unsigned*)&h1;
        *(uint2*)&As[r * SA + c4] = u;
    }
    __syncthreads();

    int lane = tid & 31, wid = tid >> 5;
    int wm = wid >> 2, wn = wid & 3;
    int r4 = lane >> 2, q = lane & 3;
    int m_base = wm * 64;
    int n_base = wn * 32;

    float c[4][4][4];
    #pragma unroll
    for (int i = 0; i < 4; i++)
        #pragma unroll
        for (int j = 0; j < 4; j++)
            #pragma unroll
            for (int e = 0; e < 4; e++) c[i][j][e] = 0.f;

    const __half* a_base = As + (m_base + r4) * SA + 2 * q;
    const __half* b_base = Bs + (n_base + r4) * SA + 2 * q;

    #pragma unroll 1
    for (int ks = 0; ks < 16; ks++) {
        int k0 = ks * 16;
        unsigned bf[4][2];
        #pragma unroll
        for (int j = 0; j < 4; j++) {
            bf[j][0] = *(const unsigned*)&b_base[j * 8 * SA + k0];
            bf[j][1] = *(const unsigned*)&b_base[j * 8 * SA + k0 + 8];
        }
        #pragma unroll
        for (int i = 0; i < 4; i++) {
            const __half* ap = a_base + i * 16 * SA + k0;
            unsigned a0 = *(const unsigned*)ap;
            unsigned a1 = *(const unsigned*)(ap + 8 * SA);
            unsigned a2 = *(const unsigned*)(ap + 8);
            unsigned a3 = *(const unsigned*)(ap + 8 * SA + 8);
            #pragma unroll
            for (int j = 0; j < 4; j++) {
                asm volatile(
                    "mma.sync.aligned.m16n8k16.row.col.f32.f16.f16.f32 "
                    "{%0,%1,%2,%3}, {%4,%5,%6,%7}, {%8,%9}, {%0,%1,%2,%3};"
                    : "+f"(c[i][j][0]), "+f"(c[i][j][1]),
                      "+f"(c[i][j][2]), "+f"(c[i][j][3])
                    : "r"(a0), "r"(a1), "r"(a2), "r"(a3),
                      "r"(bf[j][0]), "r"(bf[j][1]));
            }
        }
    }
    __syncthreads();

    unsigned* stage = (unsigned*)sm;
    const int SST = 68;

    #pragma unroll
    for (int i = 0; i < 4; i++) {
        int mr = m_base + i * 16 + r4;
        float psl = 0.f, pdl = 0.f, psh = 0.f, pdh = 0.f;
        #pragma unroll
        for (int j = 0; j < 4; j++) {
            int col = n_base + j * 8 + 2 * q;
            float sa0 = ssa[col], sa1 = ssa[col + 1];
            float sd0 = ssd[col], sd1 = ssd[col + 1];
            psl += c[i][j][0] * sa0 + c[i][j][1] * sa1;
            pdl += c[i][j][0] * sd0 + c[i][j][1] * sd1;
            psh += c[i][j][2] * sa0 + c[i][j][3] * sa1;
            pdh += c[i][j][2] * sd0 + c[i][j][3] * sd1;
            __half2 lo = __floats2half2_rn(c[i][j][0], c[i][j][1]);
            __half2 hi = __floats2half2_rn(c[i][j][2], c[i][j][3]);
            stage[mr * SST + ((n_base + j * 8) >> 1) + q]       = *(unsigned*)&lo;
            stage[(mr + 8) * SST + ((n_base + j * 8) >> 1) + q] = *(unsigned*)&hi;
        }
        #pragma unroll
        for (int o = 1; o < 4; o <<= 1) {
            psl += __shfl_xor_sync(0xffffffffu, psl, o);
            pdl += __shfl_xor_sync(0xffffffffu, pdl, o);
            psh += __shfl_xor_sync(0xffffffffu, psh, o);
            pdh += __shfl_xor_sync(0xffffffffu, pdh, o);
        }
        if (q == 0) {
            int gl = row0 + mr, gh = gl + 8;
            if (gl < N_NODES) {
                ((float*)&g_as1[gl])[wn] = psl;
                ((float*)&g_ad1[gl])[wn] = pdl;
            }
            if (gh < N_NODES) {
                ((float*)&g_as1[gh])[wn] = psh;
                ((float*)&g_ad1[gh])[wn] = pdh;
            }
        }
    }
    __syncthreads();

    unsigned* gx = (unsigned*)g_xp1h;
    for (int idx = tid; idx < 128 * 64; idx += 256) {
        int r = idx >> 6, cc = idx & 63;
        int gr = row0 + r;
        if (gr < N_NODES) gx[gr * 64 + cc] = stage[r * SST + cc];
    }
}

// ---------------- CSR build: rank pass + 2-phase scan + placement --------------
__global__ void rank_k(const void* __restrict__ eiv) {
    int i4 = (blockIdx.x * blockDim.x + threadIdx.x) * 4;
    if (i4 >= N_EDGES) return;
    int d0, d1, d2, d3;
    if (g_is64) {
        const longlong2* p = (const longlong2*)eiv + (N_EDGES + i4) / 2;
        longlong2 q0 = p[0], q1 = p[1];
        d0 = (int)q0.x; d1 = (int)q0.y; d2 = (int)q1.x; d3 = (int)q1.y;
    } else {
        int4 v = *((const int4*)((const int*)eiv + N_EDGES + i4));
        d0 = v.x; d1 = v.y; d2 = v.z; d3 = v.w;
    }
    int4 r;
    r.x = atomicAdd(&g_cnt[d0], 1);
    r.y = atomicAdd(&g_cnt[d1], 1);
    r.z = atomicAdd(&g_cnt[d2], 1);
    r.w = atomicAdd(&g_cnt[d3], 1);
    *(int4*)&g_rankv[i4] = r;
}

__global__ __launch_bounds__(256) void scanA_k() {
    __shared__ int smem8[8];
    int i = blockIdx.x * 256 + threadIdx.x;
    int v = (i < N_NODES) ? g_cnt[i] + 1 : 0;   // +1 self-loop at row end
    int incl = block_scan_incl_256(v, smem8);
    if (i < N_NODES) g_excl[i] = incl - v;
    if (threadIdx.x == 255) g_bsum[blockIdx.x] = incl;
}

// scanC: warp 0 computes this block's prefix over g_bsum[0..bid) with a strided
// warp sum (no 256-wide reduce tree, single __syncthreads).
__global__ __launch_bounds__(256) void scanC_k() {
    __shared__ int s_prefix;
    int bid = blockIdx.x, t = threadIdx.x;
    if (t < 32) {
        int acc = 0;
        for (int j = t; j < bid; j += 32) acc += g_bsum[j];
        #pragma unroll
        for (int o = 16; o > 0; o >>= 1)
            acc += __shfl_xor_sync(0xffffffffu, acc, o);
        if (t == 0) s_prefix = acc;
    }
    __syncthreads();
    int prefix = s_prefix;
    int i = bid * 256 + t;
    if (i < N_NODES) {
        int r = g_excl[i] + prefix;
        g_rowstart[i] = r;
        g_srcs[r + g_cnt[i]] = i;     // self-loop slot (last in row)
    }
    if (bid == NB_SCAN - 1 && t == 0)
        g_rowstart[N_NODES] = prefix + g_bsum[bid];   // == E_TOT
}

// placement: no atomics, position = rowstart[dst] + rank
__global__ void place_k(const void* __restrict__ eiv) {
    int i4 = (blockIdx.x * blockDim.x + threadIdx.x) * 4;
    if (i4 >= N_EDGES) return;
    int s0, s1, s2, s3, d0, d1, d2, d3;
    if (g_is64) {
        const longlong2* ps = (const longlong2*)eiv + i4 / 2;
        const longlong2* pd = (const longlong2*)eiv + (N_EDGES + i4) / 2;
        longlong2 a0 = ps[0], a1 = ps[1], b0 = pd[0], b1 = pd[1];
        s0 = (int)a0.x; s1 = (int)a0.y; s2 = (int)a1.x; s3 = (int)a1.y;
        d0 = (int)b0.x; d1 = (int)b0.y; d2 = (int)b1.x; d3 = (int)b1.y;
    } else {
        int4 sv = *((const int4*)((const int*)eiv + i4));
        int4 dv = *((const int4*)((const int*)eiv + N_EDGES + i4));
        s0 = sv.x; s1 = sv.y; s2 = sv.z; s3 = sv.w;
        d0 = dv.x; d1 = dv.y; d2 = dv.z; d3 = dv.w;
    }
    int4 r = *(const int4*)&g_rankv[i4];
    g_srcs[g_rowstart[d0] + r.x] = s0;
    g_srcs[g_rowstart[d1] + r.y] = s1;
    g_srcs[g_rowstart[d2] + r.z] = s2;
    g_srcs[g_rowstart[d3] + r.w] = s3;
}

// ---------------- layer-1 gather (validated R13 form) ---------------------------
__global__ __launch_bounds__(256) void gather1_k(
    const float* __restrict__ b1, const float* __restrict__ W2,
    const float* __restrict__ aS2, const float* __restrict__ aD2)
{
    __shared__ float4 sw[8][32];
    __shared__ int    ssrc[8][32];
    int wslot = threadIdx.x >> 5;
    int gw = (blockIdx.x * blockDim.x + threadIdx.x) >> 5;
    int l = threadIdx.x & 31;
    if (gw >= N_NODES) return;
    int rs = g_rowstart[gw], re = g_rowstart[gw + 1];
    float4 ad = g_ad1[gw];

    int h  = l >> 4;
    int hl = l & 15;
    int head = hl >> 2;

    float z = 0.f;
    float c[8];
    #pragma unroll
    for (int i = 0; i < 8; i++) c[i] = 0.f;

    for (int jc = rs; jc < re; jc += 32) {
        int idx = jc + l;
        if (idx < re) {
            int s = g_srcs[idx];
            float4 a = g_as1[s];
            sw[wslot][l] = make_float4(__expf(leaky(a.x + ad.x)),
                                       __expf(leaky(a.y + ad.y)),
                                       __expf(leaky(a.z + ad.z)),
                                       __expf(leaky(a.w + ad.w)));
            ssrc[wslot][l] = s;
        }
        __syncwarp();
        int cnt = re - jc; if (cnt > 32) cnt = 32;
        #pragma unroll 4
        for (int e = h; e < cnt; e += 2) {
            int s = ssrc[wslot][e];
            float4 w4 = sw[wslot][e];
            float wv = (head == 0) ? w4.x : (head == 1) ? w4.y
                     : (head == 2) ? w4.z : w4.w;
            uint4 pk = *(const uint4*)&g_xp1h[s * HID + 8 * hl];
            float2 f0 = __half22float2(*(__half2*)&pk.x);
            float2 f1 = __half22float2(*(__half2*)&pk.y);
            float2 f2 = __half22float2(*(__half2*)&pk.z);
            float2 f3 = __half22float2(*(__half2*)&pk.w);
            z += wv;
            c[0] += wv * f0.x; c[1] += wv * f0.y;
            c[2] += wv * f1.x; c[3] += wv * f1.y;
            c[4] += wv * f2.x; c[5] += wv * f2.y;
            c[6] += wv * f3.x; c[7] += wv * f3.y;
        }
        __syncwarp();
    }

    z += __shfl_xor_sync(0xffffffffu, z, 16);
    #pragma unroll
    for (int i = 0; i < 8; i++) c[i] += __shfl_xor_sync(0xffffffffu, c[i], 16);

    float inv = 1.0f / (z + 1e-16f);
    float4 bA = *(const float4*)&b1[8 * hl];
    float4 bB = *(const float4*)&b1[8 * hl + 4];
    float hh[8];
    hh[0] = c[0] * inv + bA.x; hh[1] = c[1] * inv + bA.y;
    hh[2] = c[2] * inv + bA.z; hh[3] = c[3] * inv + bA.w;
    hh[4] = c[4] * inv + bB.x; hh[5] = c[5] * inv + bB.y;
    hh[6] = c[6] * inv + bB.z; hh[7] = c[7] * inv + bB.w;
    #pragma unroll
    for (int i = 0; i < 8; i++) hh[i] = hh[i] > 0.f ? hh[i] : expm1f(hh[i]);

    float p0 = 0.f, p1 = 0.f;
    #pragma unroll
    for (int i = 0; i < 8; i += 2) {
        float4 w = *(const float4*)&W2[(8 * hl + i) * 2];
        p0 += hh[i] * w.x + hh[i + 1] * w.z;
        p1 += hh[i] * w.y + hh[i + 1] * w.w;
    }
    #pragma unroll
    for (int o = 8; o > 0; o >>= 1) {
        p0 += __shfl_xor_sync(0xffffffffu, p0, o);
        p1 += __shfl_xor_sync(0xffffffffu, p1, o);
    }
    if (l == 0) {
        float as2 = p0 * aS2[0] + p1 * aS2[1];
        float ad2 = p0 * aD2[0] + p1 * aD2[1];
        g_n2[gw] = make_float4(p0, p1, as2, ad2);
    }
}

// ---------------- layer-2 gather + output -------------------------------------
__global__ __launch_bounds__(256) void gather2_k(
    const float* __restrict__ b2, float* __restrict__ out)
{
    int gw = (blockIdx.x * blockDim.x + threadIdx.x) >> 5;
    int l = threadIdx.x & 31;
    if (gw >= N_NODES) return;
    int rs = g_rowstart[gw], re = g_rowstart[gw + 1];
    float ad = g_n2[gw].w;

    float z = 0.f, a0 = 0.f, a1 = 0.f;
    for (int j = rs + l; j < re; j += 32) {
        int s = __ldg(&g_srcs[j]);
        float4 n = __ldg(&g_n2[s]);
        float w = __expf(leaky(n.z + ad));
        z += w; a0 += w * n.x; a1 += w * n.y;
    }
    #pragma unroll
    for (int o = 16; o > 0; o >>= 1) {
        z  += __shfl_xor_sync(0xffffffffu, z, o);
        a0 += __shfl_xor_sync(0xffffffffu, a0, o);
        a1 += __shfl_xor_sync(0xffffffffu, a1, o);
    }
    if (l == 0) {
        float inv = 1.0f / (z + 1e-16f);
        out[gw * 2]     = a0 * inv + b2[0];
        out[gw * 2 + 1] = a1 * inv + b2[1];
    }
}

// ---------------- launch: R13 structure ----------------------------------------
extern "C" void kernel_launch(void* const* d_in, const int* in_sizes, int n_in,
                              void* d_out, int out_size) {
    const float* x     = (const float*)d_in[0];
    const float* fi    = (const float*)d_in[1];
    const float* W1    = (const float*)d_in[2];
    const float* attS1 = (const float*)d_in[3];
    const float* attD1 = (const float*)d_in[4];
    const float* b1    = (const float*)d_in[5];
    const float* W2    = (const float*)d_in[6];
    const float* attS2 = (const float*)d_in[7];
    const float* attD2 = (const float*)d_in[8];
    const float* b2    = (const float*)d_in[9];
    const void*  ei    = (const void*)d_in[10];
    float* out = (float*)d_out;

    static cudaStream_t s2 = nullptr;
    static cudaEvent_t evFork = nullptr, evJoin = nullptr;
    if (s2 == nullptr) {
        cudaStreamCreateWithFlags(&s2, cudaStreamNonBlocking);
        cudaEventCreateWithFlags(&evFork, cudaEventDisableTiming);
        cudaEventCreateWithFlags(&evJoin, cudaEventDisableTiming);
        cudaFuncSetAttribute(gemm_mma_k, cudaFuncAttributeMaxDynamicSharedMemorySize, GEMM_SMEM);
    }

    int prep_threads = (N_NODES > IN_DIM * HID) ? N_NODES : IN_DIM * HID;
    prep_k<<<(prep_threads + 255) / 256, 256>>>(W1, fi, (const int*)ei);

    // fork after prep: chain B (CSR build) on s2, concurrent with the GEMM
    cudaEventRecord(evFork, 0);
    cudaStreamWaitEvent(s2, evFork, 0);
    rank_k<<<(N_EDGES / 4 + 255) / 256, 256, 0, s2>>>(ei);
    scanA_k<<<NB_SCAN, 256, 0, s2>>>();
    scanC_k<<<NB_SCAN, 256, 0, s2>>>();
    place_k<<<(N_EDGES / 4 + 255) / 256, 256, 0, s2>>>(ei);
    cudaEventRecord(evJoin, s2);

    // chain A on capture stream
    gemm_mma_k<<<(N_NODES + 127) / 128, 256, GEMM_SMEM>>>(x, attS1, attD1);

    // join: gathers need both chains
    cudaStreamWaitEvent(0, evJoin, 0);
    gather1_k<<<(N_NODES * 32 + 255) / 256, 256>>>(b1, W2, attS2, attD2);
    gather2_k<<<(N_NODES * 32 + 255) / 256, 256>>>(b2, out);
}

// round 17
// speedup vs baseline: 1.1188x; 1.0389x over previous
#include <cuda_runtime.h>
#include <cuda_fp16.h>
#include <math.h>
#include <stdint.h>

#define N_NODES 50000
#define N_EDGES 1600000
#define E_TOT   (N_EDGES + N_NODES)
#define IN_DIM  256
#define HID     128
#define HEADS   4
#define OUT_DIM 2
#define NEG_SLOPE 0.2f
#define NB_SCAN ((N_NODES + 255) / 256)   // 196

#define SA 264                        // smem row stride in halves (528B)
#define GEMM_SMEM (2 * 128 * SA * 2)  // A + B tiles = 135168 B

// ---------------- device scratch ---------------------------------------------
__device__ __half  g_xp1h[N_NODES * HID];
__device__ float4  g_as1[N_NODES];
__device__ float4  g_ad1[N_NODES];
__device__ float4  g_n2[N_NODES];
__device__ __half  g_wth[128 * SA];
__device__ float   g_sigf[IN_DIM];
__device__ int     g_cnt[N_NODES];
__device__ int     g_rowstart[N_NODES];
__device__ int     g_rankv[N_EDGES];
__device__ int     g_srcs[E_TOT];
__device__ int     g_alloc;               // global slot allocator
__device__ int     g_is64;

__device__ __forceinline__ float leaky(float e) { return e > 0.f ? e : NEG_SLOPE * e; }

__device__ __forceinline__ int block_scan_incl_256(int v, int* smem8) {
    int lane = threadIdx.x & 31, wid = threadIdx.x >> 5;
    int x = v;
    #pragma unroll
    for (int o = 1; o < 32; o <<= 1) {
        int y = __shfl_up_sync(0xffffffffu, x, o);
        if (lane >= o) x += y;
    }
    if (lane == 31) smem8[wid] = x;
    __syncthreads();
    if (wid == 0 && lane < 8) {
        int w = smem8[lane];
        #pragma unroll
        for (int o = 1; o < 8; o <<= 1) {
            int y = __shfl_up_sync(0xffu, w, o);
            if (lane >= o) w += y;
        }
        smem8[lane] = w;
    }
    __syncthreads();
    if (wid > 0) x += smem8[wid - 1];
    return x;
}

// ---------------- prep: W1^T -> fp16, sigmoid(fi), zero cnt/alloc, probe ------
__global__ void prep_k(const float* __restrict__ W1, const float* __restrict__ fi,
                       const int* __restrict__ ei32) {
    int i = blockIdx.x * 256 + threadIdx.x;
    if (i < IN_DIM * HID) {
        int k = i >> 7, n = i & 127;
        g_wth[n * SA + k] = __float2half_rn(W1[i]);
    }
    if (i < IN_DIM) g_sigf[i] = 1.0f / (1.0f + __expf(-fi[i]));
    if (i < N_NODES) g_cnt[i] = 0;
    if (i == 0) {
        g_alloc = 0;
        int all0 = 1;
        for (int k = 0; k < 64; k++)
            if (ei32[2 * k + 1] != 0) all0 = 0;
        g_is64 = all0;   // int64 node ids < 50000 -> odd words all zero
    }
}

// ---------------- layer-1 GEMM: warp-level mma.sync ----------------------------
__global__ __launch_bounds__(256, 1) void gemm_mma_k(
    const float* __restrict__ x,
    const float* __restrict__ attS, const float* __restrict__ attD)
{
    extern __shared__ __half sm[];
    __half* As = sm;                 // [128][SA]
    __half* Bs = sm + 128 * SA;      // [128][SA]
    __shared__ float sigf[IN_DIM];
    __shared__ float ssa[HID], ssd[HID];

    int tid = threadIdx.x;
    sigf[tid] = g_sigf[tid];
    if (tid < HID) { ssa[tid] = attS[tid]; ssd[tid] = attD[tid]; }

    {
        const uint4* wsrc = (const uint4*)g_wth;
        uint4* bd = (uint4*)Bs;
        #pragma unroll 4
        for (int i = tid; i < 128 * SA / 8; i += 256) bd[i] = wsrc[i];
    }
    __syncthreads();

    int row0 = blockIdx.x * 128;
    for (int f4 = tid; f4 < 8192; f4 += 256) {
        int r = f4 >> 6, c4 = (f4 & 63) * 4;
        int gr = row0 + r;
        float4 v = make_float4(0.f, 0.f, 0.f, 0.f);
        if (gr < N_NODES) v = *(const float4*)&x[(size_t)gr * IN_DIM + c4];
        float4 s = *(float4*)&sigf[c4];
        __half2 h0 = __floats2half2_rn(v.x * s.x, v.y * s.y);
        __half2 h1 = __floats2half2_rn(v.z * s.z, v.w * s.w);
        uint2 u;
        u.x = *(unsigned*)&h0;
        u.y = *(unsigned*)&h1;
        *(uint2*)&As[r * SA + c4] = u;
    }
    __syncthreads();

    int lane = tid & 31, wid = tid >> 5;
    int wm = wid >> 2, wn = wid & 3;
    int r4 = lane >> 2, q = lane & 3;
    int m_base = wm * 64;
    int n_base = wn * 32;

    float c[4][4][4];
    #pragma unroll
    for (int i = 0; i < 4; i++)
        #pragma unroll
        for (int j = 0; j < 4; j++)
            #pragma unroll
            for (int e = 0; e < 4; e++) c[i][j][e] = 0.f;

    const __half* a_base = As + (m_base + r4) * SA + 2 * q;
    const __half* b_base = Bs + (n_base + r4) * SA + 2 * q;

    #pragma unroll 1
    for (int ks = 0; ks < 16; ks++) {
        int k0 = ks * 16;
        unsigned bf[4][2];
        #pragma unroll
        for (int j = 0; j < 4; j++) {
            bf[j][0] = *(const unsigned*)&b_base[j * 8 * SA + k0];
            bf[j][1] = *(const unsigned*)&b_base[j * 8 * SA + k0 + 8];
        }
        #pragma unroll
        for (int i = 0; i < 4; i++) {
            const __half* ap = a_base + i * 16 * SA + k0;
            unsigned a0 = *(const unsigned*)ap;
            unsigned a1 = *(const unsigned*)(ap + 8 * SA);
            unsigned a2 = *(const unsigned*)(ap + 8);
            unsigned a3 = *(const unsigned*)(ap + 8 * SA + 8);
            #pragma unroll
            for (int j = 0; j < 4; j++) {
                asm volatile(
                    "mma.sync.aligned.m16n8k16.row.col.f32.f16.f16.f32 "
                    "{%0,%1,%2,%3}, {%4,%5,%6,%7}, {%8,%9}, {%0,%1,%2,%3};"
                    : "+f"(c[i][j][0]), "+f"(c[i][j][1]),
                      "+f"(c[i][j][2]), "+f"(c[i][j][3])
                    : "r"(a0), "r"(a1), "r"(a2), "r"(a3),
                      "r"(bf[j][0]), "r"(bf[j][1]));
            }
        }
    }
    __syncthreads();

    unsigned* stage = (unsigned*)sm;
    const int SST = 68;

    #pragma unroll
    for (int i = 0; i < 4; i++) {
        int mr = m_base + i * 16 + r4;
        float psl = 0.f, pdl = 0.f, psh = 0.f, pdh = 0.f;
        #pragma unroll
        for (int j = 0; j < 4; j++) {
            int col = n_base + j * 8 + 2 * q;
            float sa0 = ssa[col], sa1 = ssa[col + 1];
            float sd0 = ssd[col], sd1 = ssd[col + 1];
            psl += c[i][j][0] * sa0 + c[i][j][1] * sa1;
            pdl += c[i][j][0] * sd0 + c[i][j][1] * sd1;
            psh += c[i][j][2] * sa0 + c[i][j][3] * sa1;
            pdh += c[i][j][2] * sd0 + c[i][j][3] * sd1;
            __half2 lo = __floats2half2_rn(c[i][j][0], c[i][j][1]);
            __half2 hi = __floats2half2_rn(c[i][j][2], c[i][j][3]);
            stage[mr * SST + ((n_base + j * 8) >> 1) + q]       = *(unsigned*)&lo;
            stage[(mr + 8) * SST + ((n_base + j * 8) >> 1) + q] = *(unsigned*)&hi;
        }
        #pragma unroll
        for (int o = 1; o < 4; o <<= 1) {
            psl += __shfl_xor_sync(0xffffffffu, psl, o);
            pdl += __shfl_xor_sync(0xffffffffu, pdl, o);
            psh += __shfl_xor_sync(0xffffffffu, psh, o);
            pdh += __shfl_xor_sync(0xffffffffu, pdh, o);
        }
        if (q == 0) {
            int gl = row0 + mr, gh = gl + 8;
            if (gl < N_NODES) {
                ((float*)&g_as1[gl])[wn] = psl;
                ((float*)&g_ad1[gl])[wn] = pdl;
            }
            if (gh < N_NODES) {
                ((float*)&g_as1[gh])[wn] = psh;
                ((float*)&g_ad1[gh])[wn] = pdh;
            }
        }
    }
    __syncthreads();

    unsigned* gx = (unsigned*)g_xp1h;
    for (int idx = tid; idx < 128 * 64; idx += 256) {
        int r = idx >> 6, cc = idx & 63;
        int gr = row0 + r;
        if (gr < N_NODES) gx[gr * 64 + cc] = stage[r * SST + cc];
    }
}

// ---------------- CSR build: rank pass + fused alloc-scan + placement ----------
__global__ void rank_k(const void* __restrict__ eiv) {
    int i4 = (blockIdx.x * blockDim.x + threadIdx.x) * 4;
    if (i4 >= N_EDGES) return;
    int d0, d1, d2, d3;
    if (g_is64) {
        const longlong2* p = (const longlong2*)eiv + (N_EDGES + i4) / 2;
        longlong2 q0 = p[0], q1 = p[1];
        d0 = (int)q0.x; d1 = (int)q0.y; d2 = (int)q1.x; d3 = (int)q1.y;
    } else {
        int4 v = *((const int4*)((const int*)eiv + N_EDGES + i4));
        d0 = v.x; d1 = v.y; d2 = v.z; d3 = v.w;
    }
    int4 r;
    r.x = atomicAdd(&g_cnt[d0], 1);
    r.y = atomicAdd(&g_cnt[d1], 1);
    r.z = atomicAdd(&g_cnt[d2], 1);
    r.w = atomicAdd(&g_cnt[d3], 1);
    *(int4*)&g_rankv[i4] = r;
}

// fused scan: block-local scan + atomic extent reservation. Rows are placed in
// whatever order blocks reserve (CSR doesn't require node-order layout; row end
// is recovered from g_cnt in the gathers).
__global__ __launch_bounds__(256) void scanAC_k() {
    __shared__ int smem8[8];
    __shared__ int s_base;
    int i = blockIdx.x * 256 + threadIdx.x;
    int cn = (i < N_NODES) ? g_cnt[i] : 0;
    int v = (i < N_NODES) ? cn + 1 : 0;       // +1 self-loop at row end
    int incl = block_scan_incl_256(v, smem8);
    if (threadIdx.x == 255) s_base = atomicAdd(&g_alloc, incl); // incl == block total
    __syncthreads();
    if (i < N_NODES) {
        int r = s_base + incl - v;
        g_rowstart[i] = r;
        g_srcs[r + cn] = i;                   // self-loop slot (last in row)
    }
}

// placement: no atomics, position = rowstart[dst] + rank
__global__ void place_k(const void* __restrict__ eiv) {
    int i4 = (blockIdx.x * blockDim.x + threadIdx.x) * 4;
    if (i4 >= N_EDGES) return;
    int s0, s1, s2, s3, d0, d1, d2, d3;
    if (g_is64) {
        const longlong2* ps = (const longlong2*)eiv + i4 / 2;
        const longlong2* pd = (const longlong2*)eiv + (N_EDGES + i4) / 2;
        longlong2 a0 = ps[0], a1 = ps[1], b0 = pd[0], b1 = pd[1];
        s0 = (int)a0.x; s1 = (int)a0.y; s2 = (int)a1.x; s3 = (int)a1.y;
        d0 = (int)b0.x; d1 = (int)b0.y; d2 = (int)b1.x; d3 = (int)b1.y;
    } else {
        int4 sv = *((const int4*)((const int*)eiv + i4));
        int4 dv = *((const int4*)((const int*)eiv + N_EDGES + i4));
        s0 = sv.x; s1 = sv.y; s2 = sv.z; s3 = sv.w;
        d0 = dv.x; d1 = dv.y; d2 = dv.z; d3 = dv.w;
    }
    int4 r = *(const int4*)&g_rankv[i4];
    g_srcs[g_rowstart[d0] + r.x] = s0;
    g_srcs[g_rowstart[d1] + r.y] = s1;
    g_srcs[g_rowstart[d2] + r.z] = s2;
    g_srcs[g_rowstart[d3] + r.w] = s3;
}

// ---------------- layer-1 gather (R13 form; row end from cnt) ------------------
__global__ __launch_bounds__(256) void gather1_k(
    const float* __restrict__ b1, const float* __restrict__ W2,
    const float* __restrict__ aS2, const float* __restrict__ aD2)
{
    __shared__ float4 sw[8][32];
    __shared__ int    ssrc[8][32];
    int wslot = threadIdx.x >> 5;
    int gw = (blockIdx.x * blockDim.x + threadIdx.x) >> 5;
    int l = threadIdx.x & 31;
    if (gw >= N_NODES) return;
    int rs = g_rowstart[gw];
    int re = rs + g_cnt[gw] + 1;
    float4 ad = g_ad1[gw];

    int h  = l >> 4;
    int hl = l & 15;
    int head = hl >> 2;

    float z = 0.f;
    float c[8];
    #pragma unroll
    for (int i = 0; i < 8; i++) c[i] = 0.f;

    for (int jc = rs; jc < re; jc += 32) {
        int idx = jc + l;
        if (idx < re) {
            int s = g_srcs[idx];
            float4 a = g_as1[s];
            sw[wslot][l] = make_float4(__expf(leaky(a.x + ad.x)),
                                       __expf(leaky(a.y + ad.y)),
                                       __expf(leaky(a.z + ad.z)),
                                       __expf(leaky(a.w + ad.w)));
            ssrc[wslot][l] = s;
        }
        __syncwarp();
        int cnt = re - jc; if (cnt > 32) cnt = 32;
        #pragma unroll 4
        for (int e = h; e < cnt; e += 2) {
            int s = ssrc[wslot][e];
            float4 w4 = sw[wslot][e];
            float wv = (head == 0) ? w4.x : (head == 1) ? w4.y
                     : (head == 2) ? w4.z : w4.w;
            uint4 pk = *(const uint4*)&g_xp1h[s * HID + 8 * hl];
            float2 f0 = __half22float2(*(__half2*)&pk.x);
            float2 f1 = __half22float2(*(__half2*)&pk.y);
            float2 f2 = __half22float2(*(__half2*)&pk.z);
            float2 f3 = __half22float2(*(__half2*)&pk.w);
            z += wv;
            c[0] += wv * f0.x; c[1] += wv * f0.y;
            c[2] += wv * f1.x; c[3] += wv * f1.y;
            c[4] += wv * f2.x; c[5] += wv * f2.y;
            c[6] += wv * f3.x; c[7] += wv * f3.y;
        }
        __syncwarp();
    }

    z += __shfl_xor_sync(0xffffffffu, z, 16);
    #pragma unroll
    for (int i = 0; i < 8; i++) c[i] += __shfl_xor_sync(0xffffffffu, c[i], 16);

    float inv = 1.0f / (z + 1e-16f);
    float4 bA = *(const float4*)&b1[8 * hl];
    float4 bB = *(const float4*)&b1[8 * hl + 4];
    float hh[8];
    hh[0] = c[0] * inv + bA.x; hh[1] = c[1] * inv + bA.y;
    hh[2] = c[2] * inv + bA.z; hh[3] = c[3] * inv + bA.w;
    hh[4] = c[4] * inv + bB.x; hh[5] = c[5] * inv + bB.y;
    hh[6] = c[6] * inv + bB.z; hh[7] = c[7] * inv + bB.w;
    #pragma unroll
    for (int i = 0; i < 8; i++) hh[i] = hh[i] > 0.f ? hh[i] : expm1f(hh[i]);

    float p0 = 0.f, p1 = 0.f;
    #pragma unroll
    for (int i = 0; i < 8; i += 2) {
        float4 w = *(const float4*)&W2[(8 * hl + i) * 2];
        p0 += hh[i] * w.x + hh[i + 1] * w.z;
        p1 += hh[i] * w.y + hh[i + 1] * w.w;
    }
    #pragma unroll
    for (int o = 8; o > 0; o >>= 1) {
        p0 += __shfl_xor_sync(0xffffffffu, p0, o);
        p1 += __shfl_xor_sync(0xffffffffu, p1, o);
    }
    if (l == 0) {
        float as2 = p0 * aS2[0] + p1 * aS2[1];
        float ad2 = p0 * aD2[0] + p1 * aD2[1];
        g_n2[gw] = make_float4(p0, p1, as2, ad2);
    }
}

// ---------------- layer-2 gather + output -------------------------------------
__global__ __launch_bounds__(256) void gather2_k(
    const float* __restrict__ b2, float* __restrict__ out)
{
    int gw = (blockIdx.x * blockDim.x + threadIdx.x) >> 5;
    int l = threadIdx.x & 31;
    if (gw >= N_NODES) return;
    int rs = g_rowstart[gw];
    int re = rs + g_cnt[gw] + 1;
    float ad = g_n2[gw].w;

    float z = 0.f, a0 = 0.f, a1 = 0.f;
    for (int j = rs + l; j < re; j += 32) {
        int s = __ldg(&g_srcs[j]);
        float4 n = __ldg(&g_n2[s]);
        float w = __expf(leaky(n.z + ad));
        z += w; a0 += w * n.x; a1 += w * n.y;
    }
    #pragma unroll
    for (int o = 16; o > 0; o >>= 1) {
        z  += __shfl_xor_sync(0xffffffffu, z, o);
        a0 += __shfl_xor_sync(0xffffffffu, a0, o);
        a1 += __shfl_xor_sync(0xffffffffu, a1, o);
    }
    if (l == 0) {
        float inv = 1.0f / (z + 1e-16f);
        out[gw * 2]     = a0 * inv + b2[0];
        out[gw * 2 + 1] = a1 * inv + b2[1];
    }
}

// ---------------- launch: R13 structure, scanA+scanC fused ---------------------
extern "C" void kernel_launch(void* const* d_in, const int* in_sizes, int n_in,
                              void* d_out, int out_size) {
    const float* x     = (const float*)d_in[0];
    const float* fi    = (const float*)d_in[1];
    const float* W1    = (const float*)d_in[2];
    const float* attS1 = (const float*)d_in[3];
    const float* attD1 = (const float*)d_in[4];
    const float* b1    = (const float*)d_in[5];
    const float* W2    = (const float*)d_in[6];
    const float* attS2 = (const float*)d_in[7];
    const float* attD2 = (const float*)d_in[8];
    const float* b2    = (const float*)d_in[9];
    const void*  ei    = (const void*)d_in[10];
    float* out = (float*)d_out;

    static cudaStream_t s2 = nullptr;
    static cudaEvent_t evFork = nullptr, evJoin = nullptr;
    if (s2 == nullptr) {
        cudaStreamCreateWithFlags(&s2, cudaStreamNonBlocking);
        cudaEventCreateWithFlags(&evFork, cudaEventDisableTiming);
        cudaEventCreateWithFlags(&evJoin, cudaEventDisableTiming);
        cudaFuncSetAttribute(gemm_mma_k, cudaFuncAttributeMaxDynamicSharedMemorySize, GEMM_SMEM);
    }

    int prep_threads = (N_NODES > IN_DIM * HID) ? N_NODES : IN_DIM * HID;
    prep_k<<<(prep_threads + 255) / 256, 256>>>(W1, fi, (const int*)ei);

    // fork after prep: chain B (CSR build) on s2, concurrent with the GEMM
    cudaEventRecord(evFork, 0);
    cudaStreamWaitEvent(s2, evFork, 0);
    rank_k<<<(N_EDGES / 4 + 255) / 256, 256, 0, s2>>>(ei);
    scanAC_k<<<NB_SCAN, 256, 0, s2>>>();
    place_k<<<(N_EDGES / 4 + 255) / 256, 256, 0, s2>>>(ei);
    cudaEventRecord(evJoin, s2);

    // chain A on capture stream
    gemm_mma_k<<<(N_NODES + 127) / 128, 256, GEMM_SMEM>>>(x, attS1, attD1);

    // join: gathers need both chains
    cudaStreamWaitEvent(0, evJoin, 0);
    gather1_k<<<(N_NODES * 32 + 255) / 256, 256>>>(b1, W2, attS2, attD2);
    gather2_k<<<(N_NODES * 32 + 255) / 256, 256>>>(b2, out);
}